// round 1
// baseline (speedup 1.0000x reference)
#include <cuda_runtime.h>

#define MAXN 100000
#define MAXE 800000
#define MAXET (MAXN + MAXE)

// ---- scratch (device globals; no runtime allocation allowed) ----
__device__ __align__(16) float g_v    [MAXN * 64];
__device__ __align__(16) float g_as   [MAXN * 64];
__device__ __align__(16) float g_ad   [MAXN * 64];
__device__ __align__(16) float g_denom[MAXN * 64];
__device__ __align__(16) float g_outh [MAXN * 64];
__device__ __align__(16) float g_ex   [(size_t)MAXET * 64];

// vector reduction (no return) into global memory
__device__ __forceinline__ void red_add_f4(float* addr, float4 v) {
    asm volatile("red.global.add.v4.f32 [%0], {%1,%2,%3,%4};"
                 :: "l"(addr), "f"(v.x), "f"(v.y), "f"(v.z), "f"(v.w)
                 : "memory");
}

// ---------------- zero denom + outh ----------------
__global__ void zero_kernel(int n4) {
    int i = blockIdx.x * blockDim.x + threadIdx.x;
    if (i >= n4) return;
    float4 z = make_float4(0.f, 0.f, 0.f, 0.f);
    ((float4*)g_denom)[i] = z;
    ((float4*)g_outh)[i]  = z;
}

// ---------------- node projections: v / a_src / a_dst ----------------
// grid: (ceil(N/64), 3), block: 128 threads
// thread = (cg 0..15, ng 0..7) -> 8 nodes x 4 channels
__global__ void proj_kernel(const float* __restrict__ x,
                            const float* __restrict__ Wl,
                            const float* __restrict__ Wsrc,
                            const float* __restrict__ Wdst,
                            int N) {
    __shared__ float sW[64 * 64];       // [k][o]
    __shared__ float sx[64 * 68];       // transposed x: [k][node], stride 68
    const float* W  = (blockIdx.y == 0) ? Wl : (blockIdx.y == 1) ? Wsrc : Wdst;
    float* outg     = (blockIdx.y == 0) ? g_v : (blockIdx.y == 1) ? g_as : g_ad;

    int tid  = threadIdx.x;
    int base = blockIdx.x * 64;

    // W is [H=4][K=64][HD=16]; want sW[k*64 + (h*16+hd)]
    for (int g = tid; g < 4096; g += 128) {
        int h = g >> 10, k = (g >> 4) & 63, hd = g & 15;
        sW[k * 64 + h * 16 + hd] = W[g];
    }
    // x tile [64 nodes][64 ch] -> transposed shared
    for (int i = tid; i < 1024; i += 128) {
        int n = i >> 4, c4 = i & 15;
        int node = base + n;
        float4 xv = (node < N) ? *(const float4*)(x + (size_t)node * 64 + c4 * 4)
                               : make_float4(0.f, 0.f, 0.f, 0.f);
        int c = c4 * 4;
        sx[(c + 0) * 68 + n] = xv.x;
        sx[(c + 1) * 68 + n] = xv.y;
        sx[(c + 2) * 68 + n] = xv.z;
        sx[(c + 3) * 68 + n] = xv.w;
    }
    __syncthreads();

    int cg = tid & 15, ng = tid >> 4;
    float4 acc[8];
#pragma unroll
    for (int i = 0; i < 8; i++) acc[i] = make_float4(0.f, 0.f, 0.f, 0.f);

#pragma unroll 4
    for (int k = 0; k < 64; k++) {
        float4 w  = *(float4*)(sW + k * 64 + cg * 4);
        float4 xa = *(float4*)(sx + k * 68 + ng * 8);
        float4 xb = *(float4*)(sx + k * 68 + ng * 8 + 4);
        float xv[8] = {xa.x, xa.y, xa.z, xa.w, xb.x, xb.y, xb.z, xb.w};
#pragma unroll
        for (int i = 0; i < 8; i++) {
            acc[i].x += xv[i] * w.x;
            acc[i].y += xv[i] * w.y;
            acc[i].z += xv[i] * w.z;
            acc[i].w += xv[i] * w.w;
        }
    }
#pragma unroll
    for (int i = 0; i < 8; i++) {
        int node = base + ng * 8 + i;
        if (node < N)
            *(float4*)(outg + (size_t)node * 64 + cg * 4) = acc[i];
    }
}

// ---------------- edge helpers ----------------
__device__ __forceinline__ float4 compute_delta(int s, int d, int l,
                                                const float* __restrict__ pos,
                                                const float* __restrict__ Wpos,
                                                const float* __restrict__ bpos) {
    float rx = 0.f, ry = 0.f, rz = 0.f;
    if (s != d) {
        rx = pos[d * 3 + 0] - pos[s * 3 + 0];
        ry = pos[d * 3 + 1] - pos[s * 3 + 1];
        rz = pos[d * 3 + 2] - pos[s * 3 + 2];
    }
    int h = l >> 2, hd0 = (l & 3) * 4;
    float4 wx = *(const float4*)(Wpos + h * 48 + hd0);
    float4 wy = *(const float4*)(Wpos + h * 48 + 16 + hd0);
    float4 wz = *(const float4*)(Wpos + h * 48 + 32 + hd0);
    float4 b  = *(const float4*)(bpos + h * 16 + hd0);
    float4 dl;
    dl.x = b.x + rx * wx.x + ry * wy.x + rz * wz.x;
    dl.y = b.y + rx * wx.y + ry * wy.y + rz * wz.y;
    dl.z = b.z + rx * wx.z + ry * wy.z + rz * wz.z;
    dl.w = b.w + rx * wx.w + ry * wy.w + rz * wz.w;
    return dl;
}

// ---------------- edge pass 1: ex = exp(alpha), denom += ex ----------------
// 16 lanes per edge, float4 per lane
__global__ void edge_alpha_kernel(const int* __restrict__ ei,
                                  const float* __restrict__ pos,
                                  const float* __restrict__ Wpos,
                                  const float* __restrict__ bpos,
                                  int E, int Et) {
    int gid = blockIdx.x * 256 + threadIdx.x;
    int e = gid >> 4;
    if (e >= Et) return;
    int l = gid & 15;
    int s, d;
    if (e < E) { s = ei[e]; d = ei[E + e]; }
    else       { s = d = e - E; }

    float4 dl = compute_delta(s, d, l, pos, Wpos, bpos);
    float4 ad = ((const float4*)g_ad)[(size_t)d * 16 + l];
    float4 as = ((const float4*)g_as)[(size_t)s * 16 + l];
    float4 ex;
    ex.x = __expf(ad.x - as.x + dl.x);
    ex.y = __expf(ad.y - as.y + dl.y);
    ex.z = __expf(ad.z - as.z + dl.z);
    ex.w = __expf(ad.w - as.w + dl.w);
    ((float4*)g_ex)[(size_t)e * 16 + l] = ex;
    red_add_f4(g_denom + (size_t)d * 64 + l * 4, ex);
}

// ---------------- edge pass 2: outh += ex * (v[src] + delta) ----------------
__global__ void edge_msg_kernel(const int* __restrict__ ei,
                                const float* __restrict__ pos,
                                const float* __restrict__ Wpos,
                                const float* __restrict__ bpos,
                                int E, int Et) {
    int gid = blockIdx.x * 256 + threadIdx.x;
    int e = gid >> 4;
    if (e >= Et) return;
    int l = gid & 15;
    int s, d;
    if (e < E) { s = ei[e]; d = ei[E + e]; }
    else       { s = d = e - E; }

    float4 dl = compute_delta(s, d, l, pos, Wpos, bpos);
    float4 ex = ((const float4*)g_ex)[(size_t)e * 16 + l];
    float4 v  = ((const float4*)g_v)[(size_t)s * 16 + l];
    float4 m;
    m.x = ex.x * (v.x + dl.x);
    m.y = ex.y * (v.y + dl.y);
    m.z = ex.z * (v.z + dl.z);
    m.w = ex.w * (v.w + dl.w);
    red_add_f4(g_outh + (size_t)d * 64 + l * 4, m);
}

// ---------------- MLP: t = outh/denom; y = relu(t@W1+b1)@W2+b2 ----------------
// grid: ceil(N/64), block 128
__global__ void mlp_kernel(const float* __restrict__ W1,
                           const float* __restrict__ b1,
                           const float* __restrict__ W2,
                           const float* __restrict__ b2,
                           float* __restrict__ out, int N) {
    __shared__ float sW[64 * 64];
    __shared__ float sx[64 * 68];
    int tid  = threadIdx.x;
    int base = blockIdx.x * 64;

    // stage t = outh/denom, transposed
    for (int i = tid; i < 1024; i += 128) {
        int n = i >> 4, c4 = i & 15;
        int node = base + n;
        float4 o4 = make_float4(0.f, 0.f, 0.f, 0.f);
        float4 d4 = make_float4(1.f, 1.f, 1.f, 1.f);
        if (node < N) {
            o4 = ((const float4*)g_outh)[(size_t)node * 16 + c4];
            d4 = ((const float4*)g_denom)[(size_t)node * 16 + c4];
        }
        int c = c4 * 4;
        sx[(c + 0) * 68 + n] = o4.x / d4.x;
        sx[(c + 1) * 68 + n] = o4.y / d4.y;
        sx[(c + 2) * 68 + n] = o4.z / d4.z;
        sx[(c + 3) * 68 + n] = o4.w / d4.w;
    }
    for (int g = tid; g < 4096; g += 128) sW[g] = W1[g];
    __syncthreads();

    int cg = tid & 15, ng = tid >> 4;
    float4 bias = *(const float4*)(b1 + cg * 4);
    float4 acc[8];
#pragma unroll
    for (int i = 0; i < 8; i++) acc[i] = bias;

#pragma unroll 4
    for (int k = 0; k < 64; k++) {
        float4 w  = *(float4*)(sW + k * 64 + cg * 4);
        float4 xa = *(float4*)(sx + k * 68 + ng * 8);
        float4 xb = *(float4*)(sx + k * 68 + ng * 8 + 4);
        float xv[8] = {xa.x, xa.y, xa.z, xa.w, xb.x, xb.y, xb.z, xb.w};
#pragma unroll
        for (int i = 0; i < 8; i++) {
            acc[i].x += xv[i] * w.x;
            acc[i].y += xv[i] * w.y;
            acc[i].z += xv[i] * w.z;
            acc[i].w += xv[i] * w.w;
        }
    }
    __syncthreads();   // everyone done reading sW/sx

    // write h = relu(acc) transposed back into sx; reload sW with W2
#pragma unroll
    for (int i = 0; i < 8; i++) {
        int n = ng * 8 + i;
        sx[(cg * 4 + 0) * 68 + n] = fmaxf(acc[i].x, 0.f);
        sx[(cg * 4 + 1) * 68 + n] = fmaxf(acc[i].y, 0.f);
        sx[(cg * 4 + 2) * 68 + n] = fmaxf(acc[i].z, 0.f);
        sx[(cg * 4 + 3) * 68 + n] = fmaxf(acc[i].w, 0.f);
    }
    for (int g = tid; g < 4096; g += 128) sW[g] = W2[g];
    __syncthreads();

    float4 bias2 = *(const float4*)(b2 + cg * 4);
#pragma unroll
    for (int i = 0; i < 8; i++) acc[i] = bias2;

#pragma unroll 4
    for (int k = 0; k < 64; k++) {
        float4 w  = *(float4*)(sW + k * 64 + cg * 4);
        float4 xa = *(float4*)(sx + k * 68 + ng * 8);
        float4 xb = *(float4*)(sx + k * 68 + ng * 8 + 4);
        float xv[8] = {xa.x, xa.y, xa.z, xa.w, xb.x, xb.y, xb.z, xb.w};
#pragma unroll
        for (int i = 0; i < 8; i++) {
            acc[i].x += xv[i] * w.x;
            acc[i].y += xv[i] * w.y;
            acc[i].z += xv[i] * w.z;
            acc[i].w += xv[i] * w.w;
        }
    }
#pragma unroll
    for (int i = 0; i < 8; i++) {
        int node = base + ng * 8 + i;
        if (node < N)
            *(float4*)(out + (size_t)node * 64 + cg * 4) = acc[i];
    }
}

extern "C" void kernel_launch(void* const* d_in, const int* in_sizes, int n_in,
                              void* d_out, int out_size) {
    const float* x    = (const float*)d_in[0];
    const float* pos  = (const float*)d_in[1];
    const int*   ei   = (const int*)d_in[2];
    const float* Wl   = (const float*)d_in[3];
    const float* Wsrc = (const float*)d_in[4];
    const float* Wdst = (const float*)d_in[5];
    const float* Wpos = (const float*)d_in[6];
    const float* bpos = (const float*)d_in[7];
    const float* W1   = (const float*)d_in[8];
    const float* b1   = (const float*)d_in[9];
    const float* W2   = (const float*)d_in[10];
    const float* b2   = (const float*)d_in[11];
    float* out = (float*)d_out;

    int N  = in_sizes[0] / 64;
    int E  = in_sizes[2] / 2;
    int Et = E + N;

    int n4 = N * 16;  // float4 count per scratch array
    zero_kernel<<<(n4 + 255) / 256, 256>>>(n4);

    dim3 pg((N + 63) / 64, 3);
    proj_kernel<<<pg, 128>>>(x, Wl, Wsrc, Wdst, N);

    int eg = (Et * 16 + 255) / 256;
    edge_alpha_kernel<<<eg, 256>>>(ei, pos, Wpos, bpos, E, Et);
    edge_msg_kernel<<<eg, 256>>>(ei, pos, Wpos, bpos, E, Et);

    mlp_kernel<<<(N + 63) / 64, 128>>>(W1, b1, W2, b2, out, N);
}

// round 2
// speedup vs baseline: 1.3009x; 1.3009x over previous
#include <cuda_runtime.h>

#define MAXN 100000

// ---- scratch (device globals; no runtime allocation allowed) ----
// g_sv: per node [a_src(64) | v(64)] interleaved -> one contiguous 512B src-gather region
__device__ __align__(16) float g_sv   [MAXN * 128];
__device__ __align__(16) float g_ad   [MAXN * 64];
__device__ __align__(16) float g_denom[MAXN * 64];
__device__ __align__(16) float g_outh [MAXN * 64];

// vector reduction (no return) into global memory
__device__ __forceinline__ void red_add_f4(float* addr, float4 v) {
    asm volatile("red.global.add.v4.f32 [%0], {%1,%2,%3,%4};"
                 :: "l"(addr), "f"(v.x), "f"(v.y), "f"(v.z), "f"(v.w)
                 : "memory");
}

// ---------------- node projections: v / a_src / a_dst (+ zero denom/outh) ----
// grid: (ceil(N/64), 3), block: 128 threads
// thread = (cg 0..15, ng 0..7) -> 8 nodes x 4 channels
__global__ void proj_kernel(const float* __restrict__ x,
                            const float* __restrict__ Wl,
                            const float* __restrict__ Wsrc,
                            const float* __restrict__ Wdst,
                            int N) {
    __shared__ float sW[64 * 64];       // [k][o]
    __shared__ float sx[64 * 68];       // transposed x: [k][node], stride 68
    int by = blockIdx.y;
    const float* W = (by == 0) ? Wl : (by == 1) ? Wsrc : Wdst;
    float* outp;   int stride;
    if (by == 0)      { outp = g_sv + 64; stride = 128; }   // v
    else if (by == 1) { outp = g_sv;      stride = 128; }   // a_src
    else              { outp = g_ad;      stride = 64;  }   // a_dst

    int tid  = threadIdx.x;
    int base = blockIdx.x * 64;

    // y==2 block also zeroes denom/outh for its node range
    if (by == 2) {
        float4 z = make_float4(0.f, 0.f, 0.f, 0.f);
        for (int i = tid; i < 1024; i += 128) {
            int n = i >> 4, c4 = i & 15;
            int node = base + n;
            if (node < N) {
                ((float4*)g_denom)[(size_t)node * 16 + c4] = z;
                ((float4*)g_outh) [(size_t)node * 16 + c4] = z;
            }
        }
    }

    // W is [H=4][K=64][HD=16]; want sW[k*64 + (h*16+hd)]
    for (int g = tid; g < 4096; g += 128) {
        int h = g >> 10, k = (g >> 4) & 63, hd = g & 15;
        sW[k * 64 + h * 16 + hd] = W[g];
    }
    // x tile [64 nodes][64 ch] -> transposed shared
    for (int i = tid; i < 1024; i += 128) {
        int n = i >> 4, c4 = i & 15;
        int node = base + n;
        float4 xv = (node < N) ? *(const float4*)(x + (size_t)node * 64 + c4 * 4)
                               : make_float4(0.f, 0.f, 0.f, 0.f);
        int c = c4 * 4;
        sx[(c + 0) * 68 + n] = xv.x;
        sx[(c + 1) * 68 + n] = xv.y;
        sx[(c + 2) * 68 + n] = xv.z;
        sx[(c + 3) * 68 + n] = xv.w;
    }
    __syncthreads();

    int cg = tid & 15, ng = tid >> 4;
    float4 acc[8];
#pragma unroll
    for (int i = 0; i < 8; i++) acc[i] = make_float4(0.f, 0.f, 0.f, 0.f);

#pragma unroll 4
    for (int k = 0; k < 64; k++) {
        float4 w  = *(float4*)(sW + k * 64 + cg * 4);
        float4 xa = *(float4*)(sx + k * 68 + ng * 8);
        float4 xb = *(float4*)(sx + k * 68 + ng * 8 + 4);
        float xv[8] = {xa.x, xa.y, xa.z, xa.w, xb.x, xb.y, xb.z, xb.w};
#pragma unroll
        for (int i = 0; i < 8; i++) {
            acc[i].x += xv[i] * w.x;
            acc[i].y += xv[i] * w.y;
            acc[i].z += xv[i] * w.z;
            acc[i].w += xv[i] * w.w;
        }
    }
#pragma unroll
    for (int i = 0; i < 8; i++) {
        int node = base + ng * 8 + i;
        if (node < N)
            *(float4*)(outp + (size_t)node * stride + cg * 4) = acc[i];
    }
}

// ---------------- edge helpers ----------------
__device__ __forceinline__ float4 compute_delta(int s, int d, int l,
                                                const float* __restrict__ pos,
                                                const float* __restrict__ Wpos,
                                                const float* __restrict__ bpos) {
    float rx = 0.f, ry = 0.f, rz = 0.f;
    if (s != d) {
        rx = pos[d * 3 + 0] - pos[s * 3 + 0];
        ry = pos[d * 3 + 1] - pos[s * 3 + 1];
        rz = pos[d * 3 + 2] - pos[s * 3 + 2];
    }
    int h = l >> 2, hd0 = (l & 3) * 4;
    float4 wx = *(const float4*)(Wpos + h * 48 + hd0);
    float4 wy = *(const float4*)(Wpos + h * 48 + 16 + hd0);
    float4 wz = *(const float4*)(Wpos + h * 48 + 32 + hd0);
    float4 b  = *(const float4*)(bpos + h * 16 + hd0);
    float4 dl;
    dl.x = b.x + rx * wx.x + ry * wy.x + rz * wz.x;
    dl.y = b.y + rx * wx.y + ry * wy.y + rz * wz.y;
    dl.z = b.z + rx * wx.z + ry * wy.z + rz * wz.z;
    dl.w = b.w + rx * wx.w + ry * wy.w + rz * wz.w;
    return dl;
}

// ---------------- fused edge pass: denom += ex; outh += ex*(v+delta) --------
// 16 lanes per edge, float4 per lane
__global__ void edge_fused_kernel(const int* __restrict__ ei,
                                  const float* __restrict__ pos,
                                  const float* __restrict__ Wpos,
                                  const float* __restrict__ bpos,
                                  int E, int Et) {
    int gid = blockIdx.x * 256 + threadIdx.x;
    int e = gid >> 4;
    if (e >= Et) return;
    int l = gid & 15;
    int s, d;
    if (e < E) { s = ei[e]; d = ei[E + e]; }
    else       { s = d = e - E; }

    float4 dl = compute_delta(s, d, l, pos, Wpos, bpos);

    float4 ad = ((const float4*)g_ad)[(size_t)d * 16 + l];
    const float4* sv = (const float4*)g_sv + (size_t)s * 32;
    float4 as = sv[l];
    float4 v  = sv[16 + l];

    float4 ex, m;
    ex.x = __expf(ad.x - as.x + dl.x);
    ex.y = __expf(ad.y - as.y + dl.y);
    ex.z = __expf(ad.z - as.z + dl.z);
    ex.w = __expf(ad.w - as.w + dl.w);
    m.x = ex.x * (v.x + dl.x);
    m.y = ex.y * (v.y + dl.y);
    m.z = ex.z * (v.z + dl.z);
    m.w = ex.w * (v.w + dl.w);

    red_add_f4(g_denom + (size_t)d * 64 + l * 4, ex);
    red_add_f4(g_outh  + (size_t)d * 64 + l * 4, m);
}

// ---------------- MLP: t = outh/denom; y = relu(t@W1+b1)@W2+b2 ----------------
// grid: ceil(N/64), block 128
__global__ void mlp_kernel(const float* __restrict__ W1,
                           const float* __restrict__ b1,
                           const float* __restrict__ W2,
                           const float* __restrict__ b2,
                           float* __restrict__ out, int N) {
    __shared__ float sW[64 * 64];
    __shared__ float sx[64 * 68];
    int tid  = threadIdx.x;
    int base = blockIdx.x * 64;

    // stage t = outh/denom, transposed
    for (int i = tid; i < 1024; i += 128) {
        int n = i >> 4, c4 = i & 15;
        int node = base + n;
        float4 o4 = make_float4(0.f, 0.f, 0.f, 0.f);
        float4 d4 = make_float4(1.f, 1.f, 1.f, 1.f);
        if (node < N) {
            o4 = ((const float4*)g_outh)[(size_t)node * 16 + c4];
            d4 = ((const float4*)g_denom)[(size_t)node * 16 + c4];
        }
        int c = c4 * 4;
        sx[(c + 0) * 68 + n] = o4.x / d4.x;
        sx[(c + 1) * 68 + n] = o4.y / d4.y;
        sx[(c + 2) * 68 + n] = o4.z / d4.z;
        sx[(c + 3) * 68 + n] = o4.w / d4.w;
    }
    for (int g = tid; g < 4096; g += 128) sW[g] = W1[g];
    __syncthreads();

    int cg = tid & 15, ng = tid >> 4;
    float4 bias = *(const float4*)(b1 + cg * 4);
    float4 acc[8];
#pragma unroll
    for (int i = 0; i < 8; i++) acc[i] = bias;

#pragma unroll 4
    for (int k = 0; k < 64; k++) {
        float4 w  = *(float4*)(sW + k * 64 + cg * 4);
        float4 xa = *(float4*)(sx + k * 68 + ng * 8);
        float4 xb = *(float4*)(sx + k * 68 + ng * 8 + 4);
        float xv[8] = {xa.x, xa.y, xa.z, xa.w, xb.x, xb.y, xb.z, xb.w};
#pragma unroll
        for (int i = 0; i < 8; i++) {
            acc[i].x += xv[i] * w.x;
            acc[i].y += xv[i] * w.y;
            acc[i].z += xv[i] * w.z;
            acc[i].w += xv[i] * w.w;
        }
    }
    __syncthreads();   // everyone done reading sW/sx

    // write h = relu(acc) transposed back into sx; reload sW with W2
#pragma unroll
    for (int i = 0; i < 8; i++) {
        int n = ng * 8 + i;
        sx[(cg * 4 + 0) * 68 + n] = fmaxf(acc[i].x, 0.f);
        sx[(cg * 4 + 1) * 68 + n] = fmaxf(acc[i].y, 0.f);
        sx[(cg * 4 + 2) * 68 + n] = fmaxf(acc[i].z, 0.f);
        sx[(cg * 4 + 3) * 68 + n] = fmaxf(acc[i].w, 0.f);
    }
    for (int g = tid; g < 4096; g += 128) sW[g] = W2[g];
    __syncthreads();

    float4 bias2 = *(const float4*)(b2 + cg * 4);
#pragma unroll
    for (int i = 0; i < 8; i++) acc[i] = bias2;

#pragma unroll 4
    for (int k = 0; k < 64; k++) {
        float4 w  = *(float4*)(sW + k * 64 + cg * 4);
        float4 xa = *(float4*)(sx + k * 68 + ng * 8);
        float4 xb = *(float4*)(sx + k * 68 + ng * 8 + 4);
        float xv[8] = {xa.x, xa.y, xa.z, xa.w, xb.x, xb.y, xb.z, xb.w};
#pragma unroll
        for (int i = 0; i < 8; i++) {
            acc[i].x += xv[i] * w.x;
            acc[i].y += xv[i] * w.y;
            acc[i].z += xv[i] * w.z;
            acc[i].w += xv[i] * w.w;
        }
    }
#pragma unroll
    for (int i = 0; i < 8; i++) {
        int node = base + ng * 8 + i;
        if (node < N)
            *(float4*)(out + (size_t)node * 64 + cg * 4) = acc[i];
    }
}

extern "C" void kernel_launch(void* const* d_in, const int* in_sizes, int n_in,
                              void* d_out, int out_size) {
    const float* x    = (const float*)d_in[0];
    const float* pos  = (const float*)d_in[1];
    const int*   ei   = (const int*)d_in[2];
    const float* Wl   = (const float*)d_in[3];
    const float* Wsrc = (const float*)d_in[4];
    const float* Wdst = (const float*)d_in[5];
    const float* Wpos = (const float*)d_in[6];
    const float* bpos = (const float*)d_in[7];
    const float* W1   = (const float*)d_in[8];
    const float* b1   = (const float*)d_in[9];
    const float* W2   = (const float*)d_in[10];
    const float* b2   = (const float*)d_in[11];
    float* out = (float*)d_out;

    int N  = in_sizes[0] / 64;
    int E  = in_sizes[2] / 2;
    int Et = E + N;

    dim3 pg((N + 63) / 64, 3);
    proj_kernel<<<pg, 128>>>(x, Wl, Wsrc, Wdst, N);

    int eg = (Et * 16 + 255) / 256;
    edge_fused_kernel<<<eg, 256>>>(ei, pos, Wpos, bpos, E, Et);

    mlp_kernel<<<(N + 63) / 64, 128>>>(W1, b1, W2, b2, out, N);
}

// round 3
// speedup vs baseline: 1.3461x; 1.0347x over previous
#include <cuda_runtime.h>

#define MAXN 100000

// ---- scratch (device globals; no runtime allocation allowed) ----
// g_sv: per node [a_src(64) | v(64)] interleaved -> one contiguous 512B src-gather region
__device__ __align__(16) float g_sv   [MAXN * 128];
__device__ __align__(16) float g_ad   [MAXN * 64];
__device__ __align__(16) float g_denom[MAXN * 64];
__device__ __align__(16) float g_outh [MAXN * 64];

// vector reduction (no return) into global memory
__device__ __forceinline__ void red_add_f4(float* addr, float4 v) {
    asm volatile("red.global.add.v4.f32 [%0], {%1,%2,%3,%4};"
                 :: "l"(addr), "f"(v.x), "f"(v.y), "f"(v.z), "f"(v.w)
                 : "memory");
}

// ---------------- node projections: v / a_src / a_dst (+ zero denom/outh) ----
// grid: (ceil(N/64), 3), block: 128 threads
// thread = (cg 0..15, ng 0..7) -> 8 nodes x 4 channels
__global__ void proj_kernel(const float* __restrict__ x,
                            const float* __restrict__ Wl,
                            const float* __restrict__ Wsrc,
                            const float* __restrict__ Wdst,
                            int N) {
    __shared__ float sW[64 * 64];       // [k][o]
    __shared__ float sx[64 * 68];       // transposed x: [k][node], stride 68
    int by = blockIdx.y;
    const float* W = (by == 0) ? Wl : (by == 1) ? Wsrc : Wdst;
    float* outp;   int stride;
    if (by == 0)      { outp = g_sv + 64; stride = 128; }   // v
    else if (by == 1) { outp = g_sv;      stride = 128; }   // a_src
    else              { outp = g_ad;      stride = 64;  }   // a_dst

    int tid  = threadIdx.x;
    int base = blockIdx.x * 64;

    // y==2 block also zeroes denom/outh for its node range
    if (by == 2) {
        float4 z = make_float4(0.f, 0.f, 0.f, 0.f);
        for (int i = tid; i < 1024; i += 128) {
            int n = i >> 4, c4 = i & 15;
            int node = base + n;
            if (node < N) {
                ((float4*)g_denom)[(size_t)node * 16 + c4] = z;
                ((float4*)g_outh) [(size_t)node * 16 + c4] = z;
            }
        }
    }

    // W is [H=4][K=64][HD=16]; want sW[k*64 + (h*16+hd)]
    for (int g = tid; g < 4096; g += 128) {
        int h = g >> 10, k = (g >> 4) & 63, hd = g & 15;
        sW[k * 64 + h * 16 + hd] = W[g];
    }
    // x tile [64 nodes][64 ch] -> transposed shared
    for (int i = tid; i < 1024; i += 128) {
        int n = i >> 4, c4 = i & 15;
        int node = base + n;
        float4 xv = (node < N) ? *(const float4*)(x + (size_t)node * 64 + c4 * 4)
                               : make_float4(0.f, 0.f, 0.f, 0.f);
        int c = c4 * 4;
        sx[(c + 0) * 68 + n] = xv.x;
        sx[(c + 1) * 68 + n] = xv.y;
        sx[(c + 2) * 68 + n] = xv.z;
        sx[(c + 3) * 68 + n] = xv.w;
    }
    __syncthreads();

    int cg = tid & 15, ng = tid >> 4;
    float4 acc[8];
#pragma unroll
    for (int i = 0; i < 8; i++) acc[i] = make_float4(0.f, 0.f, 0.f, 0.f);

#pragma unroll 4
    for (int k = 0; k < 64; k++) {
        float4 w  = *(float4*)(sW + k * 64 + cg * 4);
        float4 xa = *(float4*)(sx + k * 68 + ng * 8);
        float4 xb = *(float4*)(sx + k * 68 + ng * 8 + 4);
        float xv[8] = {xa.x, xa.y, xa.z, xa.w, xb.x, xb.y, xb.z, xb.w};
#pragma unroll
        for (int i = 0; i < 8; i++) {
            acc[i].x += xv[i] * w.x;
            acc[i].y += xv[i] * w.y;
            acc[i].z += xv[i] * w.z;
            acc[i].w += xv[i] * w.w;
        }
    }
#pragma unroll
    for (int i = 0; i < 8; i++) {
        int node = base + ng * 8 + i;
        if (node < N)
            *(float4*)(outp + (size_t)node * stride + cg * 4) = acc[i];
    }
}

// ---------------- edge helpers ----------------
__device__ __forceinline__ float4 compute_delta(int s, int d, int l,
                                                const float* __restrict__ pos,
                                                const float* __restrict__ Wpos,
                                                const float* __restrict__ bpos) {
    float rx = 0.f, ry = 0.f, rz = 0.f;
    if (s != d) {
        rx = pos[d * 3 + 0] - pos[s * 3 + 0];
        ry = pos[d * 3 + 1] - pos[s * 3 + 1];
        rz = pos[d * 3 + 2] - pos[s * 3 + 2];
    }
    int h = l >> 2, hd0 = (l & 3) * 4;
    float4 wx = *(const float4*)(Wpos + h * 48 + hd0);
    float4 wy = *(const float4*)(Wpos + h * 48 + 16 + hd0);
    float4 wz = *(const float4*)(Wpos + h * 48 + 32 + hd0);
    float4 b  = *(const float4*)(bpos + h * 16 + hd0);
    float4 dl;
    dl.x = b.x + rx * wx.x + ry * wy.x + rz * wz.x;
    dl.y = b.y + rx * wx.y + ry * wy.y + rz * wz.y;
    dl.z = b.z + rx * wx.z + ry * wy.z + rz * wz.z;
    dl.w = b.w + rx * wx.w + ry * wy.w + rz * wz.w;
    return dl;
}

// ---------------- fused edge pass: denom += ex; outh += ex*(v+delta) --------
// 16 lanes per edge, float4 per lane
__global__ void edge_fused_kernel(const int* __restrict__ ei,
                                  const float* __restrict__ pos,
                                  const float* __restrict__ Wpos,
                                  const float* __restrict__ bpos,
                                  int E, int Et) {
    int gid = blockIdx.x * 256 + threadIdx.x;
    int e = gid >> 4;
    if (e >= Et) return;
    int l = gid & 15;
    int s, d;
    if (e < E) { s = ei[e]; d = ei[E + e]; }
    else       { s = d = e - E; }

    float4 dl = compute_delta(s, d, l, pos, Wpos, bpos);

    float4 ad = ((const float4*)g_ad)[(size_t)d * 16 + l];
    const float4* sv = (const float4*)g_sv + (size_t)s * 32;
    float4 as = sv[l];
    float4 v  = sv[16 + l];

    float4 ex, m;
    ex.x = __expf(ad.x - as.x + dl.x);
    ex.y = __expf(ad.y - as.y + dl.y);
    ex.z = __expf(ad.z - as.z + dl.z);
    ex.w = __expf(ad.w - as.w + dl.w);
    m.x = ex.x * (v.x + dl.x);
    m.y = ex.y * (v.y + dl.y);
    m.z = ex.z * (v.z + dl.z);
    m.w = ex.w * (v.w + dl.w);

    red_add_f4(g_denom + (size_t)d * 64 + l * 4, ex);
    red_add_f4(g_outh  + (size_t)d * 64 + l * 4, m);
}

// ---------------- MLP: t = outh/denom; y = relu(t@W1+b1)@W2+b2 ----------------
// grid: ceil(N/64), block 128
__global__ void mlp_kernel(const float* __restrict__ W1,
                           const float* __restrict__ b1,
                           const float* __restrict__ W2,
                           const float* __restrict__ b2,
                           float* __restrict__ out, int N) {
    __shared__ float sW[64 * 64];
    __shared__ float sx[64 * 68];
    int tid  = threadIdx.x;
    int base = blockIdx.x * 64;

    // stage t = outh/denom, transposed
    for (int i = tid; i < 1024; i += 128) {
        int n = i >> 4, c4 = i & 15;
        int node = base + n;
        float4 o4 = make_float4(0.f, 0.f, 0.f, 0.f);
        float4 d4 = make_float4(1.f, 1.f, 1.f, 1.f);
        if (node < N) {
            o4 = ((const float4*)g_outh)[(size_t)node * 16 + c4];
            d4 = ((const float4*)g_denom)[(size_t)node * 16 + c4];
        }
        int c = c4 * 4;
        sx[(c + 0) * 68 + n] = o4.x / d4.x;
        sx[(c + 1) * 68 + n] = o4.y / d4.y;
        sx[(c + 2) * 68 + n] = o4.z / d4.z;
        sx[(c + 3) * 68 + n] = o4.w / d4.w;
    }
    for (int g = tid; g < 4096; g += 128) sW[g] = W1[g];
    __syncthreads();

    int cg = tid & 15, ng = tid >> 4;
    float4 bias = *(const float4*)(b1 + cg * 4);
    float4 acc[8];
#pragma unroll
    for (int i = 0; i < 8; i++) acc[i] = bias;

#pragma unroll 4
    for (int k = 0; k < 64; k++) {
        float4 w  = *(float4*)(sW + k * 64 + cg * 4);
        float4 xa = *(float4*)(sx + k * 68 + ng * 8);
        float4 xb = *(float4*)(sx + k * 68 + ng * 8 + 4);
        float xv[8] = {xa.x, xa.y, xa.z, xa.w, xb.x, xb.y, xb.z, xb.w};
#pragma unroll
        for (int i = 0; i < 8; i++) {
            acc[i].x += xv[i] * w.x;
            acc[i].y += xv[i] * w.y;
            acc[i].z += xv[i] * w.z;
            acc[i].w += xv[i] * w.w;
        }
    }
    __syncthreads();   // everyone done reading sW/sx

    // write h = relu(acc) transposed back into sx; reload sW with W2
#pragma unroll
    for (int i = 0; i < 8; i++) {
        int n = ng * 8 + i;
        sx[(cg * 4 + 0) * 68 + n] = fmaxf(acc[i].x, 0.f);
        sx[(cg * 4 + 1) * 68 + n] = fmaxf(acc[i].y, 0.f);
        sx[(cg * 4 + 2) * 68 + n] = fmaxf(acc[i].z, 0.f);
        sx[(cg * 4 + 3) * 68 + n] = fmaxf(acc[i].w, 0.f);
    }
    for (int g = tid; g < 4096; g += 128) sW[g] = W2[g];
    __syncthreads();

    float4 bias2 = *(const float4*)(b2 + cg * 4);
#pragma unroll
    for (int i = 0; i < 8; i++) acc[i] = bias2;

#pragma unroll 4
    for (int k = 0; k < 64; k++) {
        float4 w  = *(float4*)(sW + k * 64 + cg * 4);
        float4 xa = *(float4*)(sx + k * 68 + ng * 8);
        float4 xb = *(float4*)(sx + k * 68 + ng * 8 + 4);
        float xv[8] = {xa.x, xa.y, xa.z, xa.w, xb.x, xb.y, xb.z, xb.w};
#pragma unroll
        for (int i = 0; i < 8; i++) {
            acc[i].x += xv[i] * w.x;
            acc[i].y += xv[i] * w.y;
            acc[i].z += xv[i] * w.z;
            acc[i].w += xv[i] * w.w;
        }
    }
#pragma unroll
    for (int i = 0; i < 8; i++) {
        int node = base + ng * 8 + i;
        if (node < N)
            *(float4*)(out + (size_t)node * 64 + cg * 4) = acc[i];
    }
}

extern "C" void kernel_launch(void* const* d_in, const int* in_sizes, int n_in,
                              void* d_out, int out_size) {
    const float* x    = (const float*)d_in[0];
    const float* pos  = (const float*)d_in[1];
    const int*   ei   = (const int*)d_in[2];
    const float* Wl   = (const float*)d_in[3];
    const float* Wsrc = (const float*)d_in[4];
    const float* Wdst = (const float*)d_in[5];
    const float* Wpos = (const float*)d_in[6];
    const float* bpos = (const float*)d_in[7];
    const float* W1   = (const float*)d_in[8];
    const float* b1   = (const float*)d_in[9];
    const float* W2   = (const float*)d_in[10];
    const float* b2   = (const float*)d_in[11];
    float* out = (float*)d_out;

    int N  = in_sizes[0] / 64;
    int E  = in_sizes[2] / 2;
    int Et = E + N;

    dim3 pg((N + 63) / 64, 3);
    proj_kernel<<<pg, 128>>>(x, Wl, Wsrc, Wdst, N);

    int eg = (Et * 16 + 255) / 256;
    edge_fused_kernel<<<eg, 256>>>(ei, pos, Wpos, bpos, E, Et);

    mlp_kernel<<<(N + 63) / 64, 128>>>(W1, b1, W2, b2, out, N);
}

// round 4
// speedup vs baseline: 1.3506x; 1.0034x over previous
#include <cuda_runtime.h>

#define MAXN 100000

// ---- scratch (device globals; no runtime allocation allowed) ----
// g_sv: per node [a_src(64) | v(64)] interleaved -> one contiguous 512B src-gather region
__device__ __align__(16) float g_sv   [MAXN * 128];
__device__ __align__(16) float g_ad   [MAXN * 64];
__device__ __align__(16) float g_denom[MAXN * 64];
__device__ __align__(16) float g_outh [MAXN * 64];

// vector reduction (no return) into global memory
__device__ __forceinline__ void red_add_f4(float* addr, float4 v) {
    asm volatile("red.global.add.v4.f32 [%0], {%1,%2,%3,%4};"
                 :: "l"(addr), "f"(v.x), "f"(v.y), "f"(v.z), "f"(v.w)
                 : "memory");
}

// ---------------- node projections: v / a_src / a_dst (+ zero denom/outh) ----
// grid: (ceil(N/64), 3), block: 128 threads
// thread = (cg 0..15, ng 0..7) -> 8 nodes x 4 channels
__global__ void proj_kernel(const float* __restrict__ x,
                            const float* __restrict__ Wl,
                            const float* __restrict__ Wsrc,
                            const float* __restrict__ Wdst,
                            int N) {
    __shared__ float sW[64 * 64];       // [k][o]
    __shared__ float sx[64 * 68];       // transposed x: [k][node], stride 68
    int by = blockIdx.y;
    const float* W = (by == 0) ? Wl : (by == 1) ? Wsrc : Wdst;
    float* outp;   int stride;
    if (by == 0)      { outp = g_sv + 64; stride = 128; }   // v
    else if (by == 1) { outp = g_sv;      stride = 128; }   // a_src
    else              { outp = g_ad;      stride = 64;  }   // a_dst

    int tid  = threadIdx.x;
    int base = blockIdx.x * 64;

    // y==2 block also zeroes denom/outh for its node range
    if (by == 2) {
        float4 z = make_float4(0.f, 0.f, 0.f, 0.f);
        for (int i = tid; i < 1024; i += 128) {
            int n = i >> 4, c4 = i & 15;
            int node = base + n;
            if (node < N) {
                ((float4*)g_denom)[(size_t)node * 16 + c4] = z;
                ((float4*)g_outh) [(size_t)node * 16 + c4] = z;
            }
        }
    }

    // W is [H=4][K=64][HD=16]; want sW[k*64 + (h*16+hd)]
    for (int g = tid; g < 4096; g += 128) {
        int h = g >> 10, k = (g >> 4) & 63, hd = g & 15;
        sW[k * 64 + h * 16 + hd] = W[g];
    }
    // x tile [64 nodes][64 ch] -> transposed shared
    for (int i = tid; i < 1024; i += 128) {
        int n = i >> 4, c4 = i & 15;
        int node = base + n;
        float4 xv = (node < N) ? *(const float4*)(x + (size_t)node * 64 + c4 * 4)
                               : make_float4(0.f, 0.f, 0.f, 0.f);
        int c = c4 * 4;
        sx[(c + 0) * 68 + n] = xv.x;
        sx[(c + 1) * 68 + n] = xv.y;
        sx[(c + 2) * 68 + n] = xv.z;
        sx[(c + 3) * 68 + n] = xv.w;
    }
    __syncthreads();

    int cg = tid & 15, ng = tid >> 4;
    float4 acc[8];
#pragma unroll
    for (int i = 0; i < 8; i++) acc[i] = make_float4(0.f, 0.f, 0.f, 0.f);

#pragma unroll 4
    for (int k = 0; k < 64; k++) {
        float4 w  = *(float4*)(sW + k * 64 + cg * 4);
        float4 xa = *(float4*)(sx + k * 68 + ng * 8);
        float4 xb = *(float4*)(sx + k * 68 + ng * 8 + 4);
        float xv[8] = {xa.x, xa.y, xa.z, xa.w, xb.x, xb.y, xb.z, xb.w};
#pragma unroll
        for (int i = 0; i < 8; i++) {
            acc[i].x += xv[i] * w.x;
            acc[i].y += xv[i] * w.y;
            acc[i].z += xv[i] * w.z;
            acc[i].w += xv[i] * w.w;
        }
    }
#pragma unroll
    for (int i = 0; i < 8; i++) {
        int node = base + ng * 8 + i;
        if (node < N)
            *(float4*)(outp + (size_t)node * stride + cg * 4) = acc[i];
    }
}

// ---------------- edge helpers ----------------
__device__ __forceinline__ float4 compute_delta(int s, int d, int l,
                                                const float* __restrict__ pos,
                                                const float* __restrict__ Wpos,
                                                const float* __restrict__ bpos) {
    float rx = 0.f, ry = 0.f, rz = 0.f;
    if (s != d) {
        rx = pos[d * 3 + 0] - pos[s * 3 + 0];
        ry = pos[d * 3 + 1] - pos[s * 3 + 1];
        rz = pos[d * 3 + 2] - pos[s * 3 + 2];
    }
    int h = l >> 2, hd0 = (l & 3) * 4;
    float4 wx = *(const float4*)(Wpos + h * 48 + hd0);
    float4 wy = *(const float4*)(Wpos + h * 48 + 16 + hd0);
    float4 wz = *(const float4*)(Wpos + h * 48 + 32 + hd0);
    float4 b  = *(const float4*)(bpos + h * 16 + hd0);
    float4 dl;
    dl.x = b.x + rx * wx.x + ry * wy.x + rz * wz.x;
    dl.y = b.y + rx * wx.y + ry * wy.y + rz * wz.y;
    dl.z = b.z + rx * wx.z + ry * wy.z + rz * wz.z;
    dl.w = b.w + rx * wx.w + ry * wy.w + rz * wz.w;
    return dl;
}

// ---------------- fused edge pass: denom += ex; outh += ex*(v+delta) --------
// 16 lanes per edge, float4 per lane
__global__ void edge_fused_kernel(const int* __restrict__ ei,
                                  const float* __restrict__ pos,
                                  const float* __restrict__ Wpos,
                                  const float* __restrict__ bpos,
                                  int E, int Et) {
    int gid = blockIdx.x * 256 + threadIdx.x;
    int e = gid >> 4;
    if (e >= Et) return;
    int l = gid & 15;
    int s, d;
    if (e < E) { s = ei[e]; d = ei[E + e]; }
    else       { s = d = e - E; }

    float4 dl = compute_delta(s, d, l, pos, Wpos, bpos);

    float4 ad = ((const float4*)g_ad)[(size_t)d * 16 + l];
    const float4* sv = (const float4*)g_sv + (size_t)s * 32;
    float4 as = sv[l];
    float4 v  = sv[16 + l];

    float4 ex, m;
    ex.x = __expf(ad.x - as.x + dl.x);
    ex.y = __expf(ad.y - as.y + dl.y);
    ex.z = __expf(ad.z - as.z + dl.z);
    ex.w = __expf(ad.w - as.w + dl.w);
    m.x = ex.x * (v.x + dl.x);
    m.y = ex.y * (v.y + dl.y);
    m.z = ex.z * (v.z + dl.z);
    m.w = ex.w * (v.w + dl.w);

    red_add_f4(g_denom + (size_t)d * 64 + l * 4, ex);
    red_add_f4(g_outh  + (size_t)d * 64 + l * 4, m);
}

// ---------------- MLP: t = outh/denom; y = relu(t@W1+b1)@W2+b2 ----------------
// grid: ceil(N/64), block 128
__global__ void mlp_kernel(const float* __restrict__ W1,
                           const float* __restrict__ b1,
                           const float* __restrict__ W2,
                           const float* __restrict__ b2,
                           float* __restrict__ out, int N) {
    __shared__ float sW[64 * 64];
    __shared__ float sx[64 * 68];
    int tid  = threadIdx.x;
    int base = blockIdx.x * 64;

    // stage t = outh/denom, transposed
    for (int i = tid; i < 1024; i += 128) {
        int n = i >> 4, c4 = i & 15;
        int node = base + n;
        float4 o4 = make_float4(0.f, 0.f, 0.f, 0.f);
        float4 d4 = make_float4(1.f, 1.f, 1.f, 1.f);
        if (node < N) {
            o4 = ((const float4*)g_outh)[(size_t)node * 16 + c4];
            d4 = ((const float4*)g_denom)[(size_t)node * 16 + c4];
        }
        int c = c4 * 4;
        sx[(c + 0) * 68 + n] = o4.x / d4.x;
        sx[(c + 1) * 68 + n] = o4.y / d4.y;
        sx[(c + 2) * 68 + n] = o4.z / d4.z;
        sx[(c + 3) * 68 + n] = o4.w / d4.w;
    }
    for (int g = tid; g < 4096; g += 128) sW[g] = W1[g];
    __syncthreads();

    int cg = tid & 15, ng = tid >> 4;
    float4 bias = *(const float4*)(b1 + cg * 4);
    float4 acc[8];
#pragma unroll
    for (int i = 0; i < 8; i++) acc[i] = bias;

#pragma unroll 4
    for (int k = 0; k < 64; k++) {
        float4 w  = *(float4*)(sW + k * 64 + cg * 4);
        float4 xa = *(float4*)(sx + k * 68 + ng * 8);
        float4 xb = *(float4*)(sx + k * 68 + ng * 8 + 4);
        float xv[8] = {xa.x, xa.y, xa.z, xa.w, xb.x, xb.y, xb.z, xb.w};
#pragma unroll
        for (int i = 0; i < 8; i++) {
            acc[i].x += xv[i] * w.x;
            acc[i].y += xv[i] * w.y;
            acc[i].z += xv[i] * w.z;
            acc[i].w += xv[i] * w.w;
        }
    }
    __syncthreads();   // everyone done reading sW/sx

    // write h = relu(acc) transposed back into sx; reload sW with W2
#pragma unroll
    for (int i = 0; i < 8; i++) {
        int n = ng * 8 + i;
        sx[(cg * 4 + 0) * 68 + n] = fmaxf(acc[i].x, 0.f);
        sx[(cg * 4 + 1) * 68 + n] = fmaxf(acc[i].y, 0.f);
        sx[(cg * 4 + 2) * 68 + n] = fmaxf(acc[i].z, 0.f);
        sx[(cg * 4 + 3) * 68 + n] = fmaxf(acc[i].w, 0.f);
    }
    for (int g = tid; g < 4096; g += 128) sW[g] = W2[g];
    __syncthreads();

    float4 bias2 = *(const float4*)(b2 + cg * 4);
#pragma unroll
    for (int i = 0; i < 8; i++) acc[i] = bias2;

#pragma unroll 4
    for (int k = 0; k < 64; k++) {
        float4 w  = *(float4*)(sW + k * 64 + cg * 4);
        float4 xa = *(float4*)(sx + k * 68 + ng * 8);
        float4 xb = *(float4*)(sx + k * 68 + ng * 8 + 4);
        float xv[8] = {xa.x, xa.y, xa.z, xa.w, xb.x, xb.y, xb.z, xb.w};
#pragma unroll
        for (int i = 0; i < 8; i++) {
            acc[i].x += xv[i] * w.x;
            acc[i].y += xv[i] * w.y;
            acc[i].z += xv[i] * w.z;
            acc[i].w += xv[i] * w.w;
        }
    }
#pragma unroll
    for (int i = 0; i < 8; i++) {
        int node = base + ng * 8 + i;
        if (node < N)
            *(float4*)(out + (size_t)node * 64 + cg * 4) = acc[i];
    }
}

extern "C" void kernel_launch(void* const* d_in, const int* in_sizes, int n_in,
                              void* d_out, int out_size) {
    const float* x    = (const float*)d_in[0];
    const float* pos  = (const float*)d_in[1];
    const int*   ei   = (const int*)d_in[2];
    const float* Wl   = (const float*)d_in[3];
    const float* Wsrc = (const float*)d_in[4];
    const float* Wdst = (const float*)d_in[5];
    const float* Wpos = (const float*)d_in[6];
    const float* bpos = (const float*)d_in[7];
    const float* W1   = (const float*)d_in[8];
    const float* b1   = (const float*)d_in[9];
    const float* W2   = (const float*)d_in[10];
    const float* b2   = (const float*)d_in[11];
    float* out = (float*)d_out;

    int N  = in_sizes[0] / 64;
    int E  = in_sizes[2] / 2;
    int Et = E + N;

    dim3 pg((N + 63) / 64, 3);
    proj_kernel<<<pg, 128>>>(x, Wl, Wsrc, Wdst, N);

    int eg = (Et * 16 + 255) / 256;
    edge_fused_kernel<<<eg, 256>>>(ei, pos, Wpos, bpos, E, Et);

    mlp_kernel<<<(N + 63) / 64, 128>>>(W1, b1, W2, b2, out, N);
}

// round 5
// speedup vs baseline: 1.5630x; 1.1573x over previous
#include <cuda_runtime.h>

#define MAXN 100000

// ---- scratch (device globals; no runtime allocation allowed) ----
// g_sv: per node [a_src(64) | v(64)] interleaved -> one contiguous 512B src-gather region
__device__ __align__(16) float g_sv   [MAXN * 128];
__device__ __align__(16) float g_denom[MAXN * 64];
__device__ __align__(16) float g_outh [MAXN * 64];

// vector reduction (no return) into global memory
__device__ __forceinline__ void red_add_f4(float* addr, float4 v) {
    asm volatile("red.global.add.v4.f32 [%0], {%1,%2,%3,%4};"
                 :: "l"(addr), "f"(v.x), "f"(v.y), "f"(v.z), "f"(v.w)
                 : "memory");
}

// ---------------- node projections: a_src & v in one pass (+ zero denom/outh)
// grid: ceil(N/64), block: 256 threads
// thread = (cg 0..15, ng 0..15) -> 4 nodes x 4 channels, BOTH matrices
__global__ void __launch_bounds__(256) proj_kernel(
        const float* __restrict__ x,
        const float* __restrict__ Wl,
        const float* __restrict__ Wsrc,
        int N) {
    __shared__ float sWs[64 * 64];      // a_src weights [k][o]
    __shared__ float sWl[64 * 64];      // v weights     [k][o]
    __shared__ float sx [64 * 68];      // transposed x: [k][node]

    int tid  = threadIdx.x;
    int base = blockIdx.x * 64;

    // zero denom/outh for this node range (64 nodes * 16 f4 * 2 arrays / 256 thr = 8 ea)
    {
        float4 z = make_float4(0.f, 0.f, 0.f, 0.f);
        for (int i = tid; i < 1024; i += 256) {
            int n = i >> 4, c4 = i & 15;
            int node = base + n;
            if (node < N) {
                ((float4*)g_denom)[(size_t)node * 16 + c4] = z;
                ((float4*)g_outh) [(size_t)node * 16 + c4] = z;
            }
        }
    }

    // W is [H=4][K=64][HD=16]; want sW[k*64 + (h*16+hd)]
    for (int g = tid; g < 4096; g += 256) {
        int h = g >> 10, k = (g >> 4) & 63, hd = g & 15;
        int o = h * 16 + hd;
        sWs[k * 64 + o] = Wsrc[g];
        sWl[k * 64 + o] = Wl[g];
    }
    // x tile [64 nodes][64 ch] -> transposed shared
    for (int i = tid; i < 1024; i += 256) {
        int n = i >> 4, c4 = i & 15;
        int node = base + n;
        float4 xv = (node < N) ? *(const float4*)(x + (size_t)node * 64 + c4 * 4)
                               : make_float4(0.f, 0.f, 0.f, 0.f);
        int c = c4 * 4;
        sx[(c + 0) * 68 + n] = xv.x;
        sx[(c + 1) * 68 + n] = xv.y;
        sx[(c + 2) * 68 + n] = xv.z;
        sx[(c + 3) * 68 + n] = xv.w;
    }
    __syncthreads();

    int cg = tid & 15, ng = tid >> 4;
    float4 accS[4], accV[4];
#pragma unroll
    for (int i = 0; i < 4; i++) {
        accS[i] = make_float4(0.f, 0.f, 0.f, 0.f);
        accV[i] = make_float4(0.f, 0.f, 0.f, 0.f);
    }

#pragma unroll 8
    for (int k = 0; k < 64; k++) {
        float4 ws = *(float4*)(sWs + k * 64 + cg * 4);
        float4 wl = *(float4*)(sWl + k * 64 + cg * 4);
        float4 xa = *(float4*)(sx + k * 68 + ng * 4);
        float xv[4] = {xa.x, xa.y, xa.z, xa.w};
#pragma unroll
        for (int i = 0; i < 4; i++) {
            accS[i].x += xv[i] * ws.x;
            accS[i].y += xv[i] * ws.y;
            accS[i].z += xv[i] * ws.z;
            accS[i].w += xv[i] * ws.w;
            accV[i].x += xv[i] * wl.x;
            accV[i].y += xv[i] * wl.y;
            accV[i].z += xv[i] * wl.z;
            accV[i].w += xv[i] * wl.w;
        }
    }
#pragma unroll
    for (int i = 0; i < 4; i++) {
        int node = base + ng * 4 + i;
        if (node < N) {
            float* p = g_sv + (size_t)node * 128;
            *(float4*)(p + cg * 4)      = accS[i];   // a_src
            *(float4*)(p + 64 + cg * 4) = accV[i];   // v
        }
    }
}

// ---------------- edge helpers ----------------
__device__ __forceinline__ float4 compute_delta(int s, int d, int l,
                                                const float* __restrict__ pos,
                                                const float* __restrict__ Wpos,
                                                const float* __restrict__ bpos) {
    float rx = 0.f, ry = 0.f, rz = 0.f;
    if (s != d) {
        rx = pos[d * 3 + 0] - pos[s * 3 + 0];
        ry = pos[d * 3 + 1] - pos[s * 3 + 1];
        rz = pos[d * 3 + 2] - pos[s * 3 + 2];
    }
    int h = l >> 2, hd0 = (l & 3) * 4;
    float4 wx = *(const float4*)(Wpos + h * 48 + hd0);
    float4 wy = *(const float4*)(Wpos + h * 48 + 16 + hd0);
    float4 wz = *(const float4*)(Wpos + h * 48 + 32 + hd0);
    float4 b  = *(const float4*)(bpos + h * 16 + hd0);
    float4 dl;
    dl.x = b.x + rx * wx.x + ry * wy.x + rz * wz.x;
    dl.y = b.y + rx * wx.y + ry * wy.y + rz * wz.y;
    dl.z = b.z + rx * wx.z + ry * wy.z + rz * wz.z;
    dl.w = b.w + rx * wx.w + ry * wy.w + rz * wz.w;
    return dl;
}

// ---------------- fused edge pass: denom += ex; outh += ex*(v+delta) --------
// Softmax-shift invariance: the a_dst[d] term is constant per destination and
// cancels in attn = ex/denom, so it is omitted entirely.
// 16 lanes per edge, float4 per lane
__global__ void edge_fused_kernel(const int* __restrict__ ei,
                                  const float* __restrict__ pos,
                                  const float* __restrict__ Wpos,
                                  const float* __restrict__ bpos,
                                  int E, int Et) {
    int gid = blockIdx.x * 256 + threadIdx.x;
    int e = gid >> 4;
    if (e >= Et) return;
    int l = gid & 15;
    int s, d;
    if (e < E) { s = ei[e]; d = ei[E + e]; }
    else       { s = d = e - E; }

    float4 dl = compute_delta(s, d, l, pos, Wpos, bpos);

    const float4* sv = (const float4*)g_sv + (size_t)s * 32;
    float4 as = sv[l];
    float4 v  = sv[16 + l];

    float4 ex, m;
    ex.x = __expf(dl.x - as.x);
    ex.y = __expf(dl.y - as.y);
    ex.z = __expf(dl.z - as.z);
    ex.w = __expf(dl.w - as.w);
    m.x = ex.x * (v.x + dl.x);
    m.y = ex.y * (v.y + dl.y);
    m.z = ex.z * (v.z + dl.z);
    m.w = ex.w * (v.w + dl.w);

    red_add_f4(g_denom + (size_t)d * 64 + l * 4, ex);
    red_add_f4(g_outh  + (size_t)d * 64 + l * 4, m);
}

// ---------------- MLP: t = outh/denom; y = relu(t@W1+b1)@W2+b2 ----------------
// grid: ceil(N/64), block 256; thread = (cg, ng) -> 4 nodes x 4 channels
__global__ void __launch_bounds__(256) mlp_kernel(
        const float* __restrict__ W1,
        const float* __restrict__ b1,
        const float* __restrict__ W2,
        const float* __restrict__ b2,
        float* __restrict__ out, int N) {
    __shared__ float sW1[64 * 64];
    __shared__ float sW2[64 * 64];
    __shared__ float sx [64 * 68];
    int tid  = threadIdx.x;
    int base = blockIdx.x * 64;

    for (int g = tid; g < 4096; g += 256) { sW1[g] = W1[g]; sW2[g] = W2[g]; }

    // stage t = outh/denom, transposed
    for (int i = tid; i < 1024; i += 256) {
        int n = i >> 4, c4 = i & 15;
        int node = base + n;
        float4 o4 = make_float4(0.f, 0.f, 0.f, 0.f);
        float4 d4 = make_float4(1.f, 1.f, 1.f, 1.f);
        if (node < N) {
            o4 = ((const float4*)g_outh)[(size_t)node * 16 + c4];
            d4 = ((const float4*)g_denom)[(size_t)node * 16 + c4];
        }
        int c = c4 * 4;
        sx[(c + 0) * 68 + n] = o4.x / d4.x;
        sx[(c + 1) * 68 + n] = o4.y / d4.y;
        sx[(c + 2) * 68 + n] = o4.z / d4.z;
        sx[(c + 3) * 68 + n] = o4.w / d4.w;
    }
    __syncthreads();

    int cg = tid & 15, ng = tid >> 4;
    float4 bias = *(const float4*)(b1 + cg * 4);
    float4 acc[4];
#pragma unroll
    for (int i = 0; i < 4; i++) acc[i] = bias;

#pragma unroll 8
    for (int k = 0; k < 64; k++) {
        float4 w  = *(float4*)(sW1 + k * 64 + cg * 4);
        float4 xa = *(float4*)(sx + k * 68 + ng * 4);
        float xv[4] = {xa.x, xa.y, xa.z, xa.w};
#pragma unroll
        for (int i = 0; i < 4; i++) {
            acc[i].x += xv[i] * w.x;
            acc[i].y += xv[i] * w.y;
            acc[i].z += xv[i] * w.z;
            acc[i].w += xv[i] * w.w;
        }
    }
    __syncthreads();   // all reads of sx done

    // write h = relu(acc) transposed back into sx
#pragma unroll
    for (int i = 0; i < 4; i++) {
        int n = ng * 4 + i;
        sx[(cg * 4 + 0) * 68 + n] = fmaxf(acc[i].x, 0.f);
        sx[(cg * 4 + 1) * 68 + n] = fmaxf(acc[i].y, 0.f);
        sx[(cg * 4 + 2) * 68 + n] = fmaxf(acc[i].z, 0.f);
        sx[(cg * 4 + 3) * 68 + n] = fmaxf(acc[i].w, 0.f);
    }
    __syncthreads();

    float4 bias2 = *(const float4*)(b2 + cg * 4);
#pragma unroll
    for (int i = 0; i < 4; i++) acc[i] = bias2;

#pragma unroll 8
    for (int k = 0; k < 64; k++) {
        float4 w  = *(float4*)(sW2 + k * 64 + cg * 4);
        float4 xa = *(float4*)(sx + k * 68 + ng * 4);
        float xv[4] = {xa.x, xa.y, xa.z, xa.w};
#pragma unroll
        for (int i = 0; i < 4; i++) {
            acc[i].x += xv[i] * w.x;
            acc[i].y += xv[i] * w.y;
            acc[i].z += xv[i] * w.z;
            acc[i].w += xv[i] * w.w;
        }
    }
#pragma unroll
    for (int i = 0; i < 4; i++) {
        int node = base + ng * 4 + i;
        if (node < N)
            *(float4*)(out + (size_t)node * 64 + cg * 4) = acc[i];
    }
}

extern "C" void kernel_launch(void* const* d_in, const int* in_sizes, int n_in,
                              void* d_out, int out_size) {
    const float* x    = (const float*)d_in[0];
    const float* pos  = (const float*)d_in[1];
    const int*   ei   = (const int*)d_in[2];
    const float* Wl   = (const float*)d_in[3];
    const float* Wsrc = (const float*)d_in[4];
    // d_in[5] = W_dst  (unused: cancels exactly in the segment softmax)
    const float* Wpos = (const float*)d_in[6];
    const float* bpos = (const float*)d_in[7];
    const float* W1   = (const float*)d_in[8];
    const float* b1   = (const float*)d_in[9];
    const float* W2   = (const float*)d_in[10];
    const float* b2   = (const float*)d_in[11];
    float* out = (float*)d_out;

    int N  = in_sizes[0] / 64;
    int E  = in_sizes[2] / 2;
    int Et = E + N;

    proj_kernel<<<(N + 63) / 64, 256>>>(x, Wl, Wsrc, N);

    int eg = (Et * 16 + 255) / 256;
    edge_fused_kernel<<<eg, 256>>>(ei, pos, Wpos, bpos, E, Et);

    mlp_kernel<<<(N + 63) / 64, 256>>>(W1, b1, W2, b2, out, N);
}